// round 7
// baseline (speedup 1.0000x reference)
#include <cuda_runtime.h>
#include <cstdint>

#define C_  512
#define Hh  24
#define Ww  24
#define HW  576
#define NH  8
#define HD  64
#define PW  30
#define PP  900
#define KP  960
#define SE_STRIDE 968

typedef unsigned long long ull;

// Scratch (device globals: allocation-free)
__device__ float g_Xp[C_ * KP];   // reflect-padded x, keys padded to 960 (zeros)
__device__ float g_Q [C_ * HW];   // Q[o][p]
__device__ float g_K [C_ * KP];   // K[o][pp]
__device__ float g_VT[KP * C_];   // V transposed: VT[pp][o]

// ---- packed fp32x2 helpers (attention kernel) ----
__device__ __forceinline__ void fma2(ull &d, ull a, ull b) {
    asm("fma.rn.f32x2 %0, %1, %2, %0;" : "+l"(d) : "l"(a), "l"(b));
}
__device__ __forceinline__ ull pk2(float x, float y) {
    ull r; asm("mov.b64 %0, {%1, %2};" : "=l"(r) : "f"(x), "f"(y)); return r;
}
__device__ __forceinline__ float2 upk(ull v) {
    float2 r; asm("mov.b64 {%0, %1}, %2;" : "=f"(r.x), "=f"(r.y) : "l"(v)); return r;
}

// ---- tf32 tensor-core helpers ----
__device__ __forceinline__ uint32_t f2tf(float f) {
    uint32_t r; asm("cvt.rna.tf32.f32 %0, %1;" : "=r"(r) : "f"(f)); return r;
}
__device__ __forceinline__ void mma_tf32(float* c, const uint32_t* a, const uint32_t* b) {
    asm("mma.sync.aligned.m16n8k8.row.col.f32.tf32.tf32.f32 "
        "{%0,%1,%2,%3}, {%4,%5,%6,%7}, {%8,%9}, {%0,%1,%2,%3};"
        : "+f"(c[0]), "+f"(c[1]), "+f"(c[2]), "+f"(c[3])
        : "r"(a[0]), "r"(a[1]), "r"(a[2]), "r"(a[3]), "r"(b[0]), "r"(b[1]));
}

// ---------------------------------------------------------------------------
// Kernel 1: reflect-pad gather. g_Xp[c][pp] (pp = pr*30+pc), zeros for pp>=900.
// ---------------------------------------------------------------------------
__global__ void pad_kernel(const float* __restrict__ x) {
    int idx = blockIdx.x * 256 + threadIdx.x;
    if (idx >= C_ * KP) return;
    int c = idx / KP, pp = idx - c * KP;
    float v = 0.f;
    if (pp < PP) {
        int pr = pp / PW, pc = pp - pr * PW;
        int r = pr - 3; r = (r < 0) ? -r : ((r >= Hh) ? 2 * Hh - 2 - r : r);
        int cl = pc - 3; cl = (cl < 0) ? -cl : ((cl >= Ww) ? 2 * Ww - 2 - cl : cl);
        v = x[c * HW + r * Ww + cl];
    }
    g_Xp[idx] = v;
}

// ---------------------------------------------------------------------------
// Kernel 2: three conv1x1 GEMMs via mma.sync tf32 with FRAGMENT-ORDER smem.
// Staging scatters tf32 data directly into per-(subtile,ks,lane) fragment
// layout, so the inner loop is 1 LDS.128 (A) / 1 LDS.64 (B) per subtile:
// per ks-step per warp: 2 LDS.128 + 4 LDS.64 + 8 HMMA = 14 issues.
//   aF[mt 0..3][ks 0..3][lane][4]  (2048 u32 per chunk)
//   bF[nt 0..7][ks 0..3][lane][2]  (2048 u32 per chunk)
// CTA 64x64, 128 thr (2x2 warps, 32x32 warp tile), k-chunk 32, double-buffer.
// ---------------------------------------------------------------------------
__global__ void __launch_bounds__(128) gemm_all_kernel(
    const float* __restrict__ Wq, const float* __restrict__ bq,
    const float* __restrict__ Wk, const float* __restrict__ bk,
    const float* __restrict__ Wv, const float* __restrict__ bv,
    const float* __restrict__ x)
{
    __shared__ uint32_t smu[8192];   // buf0: A@0 B@2048 | buf1: A@4096 B@6144 (32KB)

    int bid = blockIdx.x;
    const float *Wm, *bias, *X; float* Cout; int N, transp = 0, nt_, ot_;
    if (bid < 72)       { nt_ = bid % 9;      ot_ = bid / 9;       Wm = Wq; bias = bq; X = x;    Cout = g_Q;  N = HW; }
    else if (bid < 192) { int b = bid - 72;   nt_ = b % 15; ot_ = b / 15; Wm = Wk; bias = bk; X = g_Xp; Cout = g_K;  N = KP; }
    else                { int b = bid - 192;  nt_ = b % 15; ot_ = b / 15; Wm = Wv; bias = bv; X = g_Xp; Cout = g_VT; N = KP; transp = 1; }
    int nB = nt_ * 64, oB = ot_ * 64;

    int tid  = threadIdx.x;
    int lane = tid & 31, wid = tid >> 5;
    int warp_m = wid & 1, warp_n = wid >> 1;     // 2x2 warps
    int grp = lane >> 2, qd = lane & 3;

    // staging thread mapping
    int arow = tid >> 1, ahalf = (tid & 1) << 4;     // A: row 0..63, k-half 0/16
    int amt = arow >> 4, agrp = arow & 7, ahl = (arow >> 3) & 1;
    int abase = (agrp << 2) * 4 + ahl;               // (grp*4+qd)*4 + half, qd added per elem
    int brow = tid >> 2, boff = (tid & 3) << 4;      // B: k-row 0..31, n-group of 16
    int bks = brow >> 3, bqd = brow & 3, bkh = (brow >> 2) & 1;

    float acc[2][4][4];
#pragma unroll
    for (int i = 0; i < 2; i++)
#pragma unroll
        for (int j = 0; j < 4; j++)
#pragma unroll
            for (int e = 0; e < 4; e++) acc[i][j][e] = 0.f;

    // ---- staging lambda-equivalent (macro-ish via code dup) ----
    // A element (row=arow, k=ahalf+j): ks=k>>3, qd=k&3, kh=(k>>2)&1
    //   -> aBuf[(amt*4+ks)*128 + (agrp*4+qd)*4 + ahl + 2*kh]
    // B element (k=brow, n=boff+j): nt=n>>3, gp=n&7
    //   -> bBuf[(nt*4+bks)*64 + (gp*4+bqd)*2 + bkh]

    // stage chunk 0
    {
        uint32_t* aB = smu;
        uint32_t* bB = smu + 2048;
        const float4* aS = (const float4*)&Wm[(oB + arow) * C_ + ahalf];
        const float4* bS = (const float4*)&X[brow * N + nB + boff];
#pragma unroll
        for (int g = 0; g < 4; g++) {
            float4 w = aS[g];
            float wv[4] = {w.x, w.y, w.z, w.w};
#pragma unroll
            for (int e = 0; e < 4; e++) {
                int k = ahalf + 4 * g + e;
                aB[((amt << 2) + (k >> 3)) * 128 + ((agrp << 2) + (k & 3)) * 4 + ahl + 2 * ((k >> 2) & 1)] = f2tf(wv[e]);
            }
        }
#pragma unroll
        for (int g = 0; g < 4; g++) {
            float4 v = bS[g];
            float vv[4] = {v.x, v.y, v.z, v.w};
#pragma unroll
            for (int e = 0; e < 4; e++) {
                int n = boff + 4 * g + e;
                bB[(((n >> 3) << 2) + bks) * 64 + (((n & 7) << 2) + bqd) * 2 + bkh] = f2tf(vv[e]);
            }
        }
    }
    __syncthreads();

    int buf = 0;
    for (int cc = 0; cc < C_; cc += 32) {
        bool pf = cc + 32 < C_;
        float4 wreg[4], xreg[4];
        if (pf) {
            const float4* aS = (const float4*)&Wm[(oB + arow) * C_ + cc + 32 + ahalf];
            const float4* bS = (const float4*)&X[(cc + 32 + brow) * N + nB + boff];
#pragma unroll
            for (int g = 0; g < 4; g++) wreg[g] = aS[g];
#pragma unroll
            for (int g = 0; g < 4; g++) xreg[g] = bS[g];
        }
        const uint32_t* cA = smu + buf * 4096;
        const uint32_t* cB = cA + 2048;
#pragma unroll
        for (int ks = 0; ks < 4; ks++) {
            uint4 a0 = *(const uint4*)&cA[(((warp_m << 1) + 0) * 4 + ks) * 128 + (lane << 2)];
            uint4 a1 = *(const uint4*)&cA[(((warp_m << 1) + 1) * 4 + ks) * 128 + (lane << 2)];
            uint2 b0 = *(const uint2*)&cB[(((warp_n << 2) + 0) * 4 + ks) * 64 + (lane << 1)];
            uint2 b1 = *(const uint2*)&cB[(((warp_n << 2) + 1) * 4 + ks) * 64 + (lane << 1)];
            uint2 b2 = *(const uint2*)&cB[(((warp_n << 2) + 2) * 4 + ks) * 64 + (lane << 1)];
            uint2 b3 = *(const uint2*)&cB[(((warp_n << 2) + 3) * 4 + ks) * 64 + (lane << 1)];
            mma_tf32(acc[0][0], (const uint32_t*)&a0, (const uint32_t*)&b0);
            mma_tf32(acc[0][1], (const uint32_t*)&a0, (const uint32_t*)&b1);
            mma_tf32(acc[0][2], (const uint32_t*)&a0, (const uint32_t*)&b2);
            mma_tf32(acc[0][3], (const uint32_t*)&a0, (const uint32_t*)&b3);
            mma_tf32(acc[1][0], (const uint32_t*)&a1, (const uint32_t*)&b0);
            mma_tf32(acc[1][1], (const uint32_t*)&a1, (const uint32_t*)&b1);
            mma_tf32(acc[1][2], (const uint32_t*)&a1, (const uint32_t*)&b2);
            mma_tf32(acc[1][3], (const uint32_t*)&a1, (const uint32_t*)&b3);
        }
        if (pf) {
            uint32_t* aB = smu + (buf ^ 1) * 4096;
            uint32_t* bB = aB + 2048;
#pragma unroll
            for (int g = 0; g < 4; g++) {
                float wv[4] = {wreg[g].x, wreg[g].y, wreg[g].z, wreg[g].w};
#pragma unroll
                for (int e = 0; e < 4; e++) {
                    int k = ahalf + 4 * g + e;
                    aB[((amt << 2) + (k >> 3)) * 128 + ((agrp << 2) + (k & 3)) * 4 + ahl + 2 * ((k >> 2) & 1)] = f2tf(wv[e]);
                }
            }
#pragma unroll
            for (int g = 0; g < 4; g++) {
                float vv[4] = {xreg[g].x, xreg[g].y, xreg[g].z, xreg[g].w};
#pragma unroll
                for (int e = 0; e < 4; e++) {
                    int n = boff + 4 * g + e;
                    bB[(((n >> 3) << 2) + bks) * 64 + (((n & 7) << 2) + bqd) * 2 + bkh] = f2tf(vv[e]);
                }
            }
        }
        __syncthreads();
        buf ^= 1;
    }

    // ---- epilogue (acc thread-mapping: row = warp_m*32+ms*16+grp(+8), col = warp_n*32+ns*8+2*qd) ----
    if (!transp) {
#pragma unroll
        for (int ms = 0; ms < 2; ms++)
#pragma unroll
            for (int part = 0; part < 2; part++) {
                int row = warp_m * 32 + ms * 16 + grp + part * 8;
                float bv_ = bias[oB + row];
#pragma unroll
                for (int ns = 0; ns < 4; ns++) {
                    float2 val = make_float2(acc[ms][ns][2 * part] + bv_,
                                             acc[ms][ns][2 * part + 1] + bv_);
                    *(float2*)&Cout[(oB + row) * N + nB + warp_n * 32 + ns * 8 + 2 * qd] = val;
                }
            }
    } else {
        float* sT = (float*)smu;                 // [n][o], 64 x 65 = 4160 <= 8192
#pragma unroll
        for (int ms = 0; ms < 2; ms++)
#pragma unroll
            for (int part = 0; part < 2; part++) {
                int row = warp_m * 32 + ms * 16 + grp + part * 8;
                float bv_ = bias[oB + row];
#pragma unroll
                for (int ns = 0; ns < 4; ns++) {
                    int n = warp_n * 32 + ns * 8 + 2 * qd;
                    sT[(n    ) * 65 + row] = acc[ms][ns][2 * part] + bv_;
                    sT[(n + 1) * 65 + row] = acc[ms][ns][2 * part + 1] + bv_;
                }
            }
        __syncthreads();
#pragma unroll
        for (int it = 0; it < 32; it++) {
            int idx = it * 128 + tid;
            int n = idx >> 6, o = idx & 63;
            Cout[(nB + n) * C_ + oB + o] = sT[n * 65 + o];
        }
    }
}

// ---------------------------------------------------------------------------
// Kernel 3: fused attention over 960 (padded) deduplicated keys with
// multiplicity-weighted softmax. Grid (18 qtiles, 8 heads) = 144 CTAs.
// Double-buffered K/V staging; full 32x960 E tile in smem.  (R2 verbatim)
// ---------------------------------------------------------------------------
__global__ void __launch_bounds__(256) attn_kernel(const float* __restrict__ x,
                            const float* __restrict__ gamma_p,
                            float* __restrict__ out) {
    extern __shared__ float sm[];
    float* sQ   = sm;                      // 64*32  = 2048 : sQ[d][q]
    float* sKV0 = sm + 2048;               // 64*68  = 4352
    float* sKV1 = sKV0 + 4352;             // 64*68  = 4352
    float* sE   = sKV1 + 4352;             // 32*968 = 30976
    float* sInv = sE + 32 * SE_STRIDE;     // 32

    int h   = blockIdx.y;
    int q0  = blockIdx.x * 32;
    int tid = threadIdx.x;
    int tx  = tid & 15, ty = tid >> 4;
    int tx4 = tx << 2;
    int dstg = tid >> 2, cstg = (tid & 3) << 4;
    float* sKVb[2] = { sKV0, sKV1 };

    // Load Q tile (d-major), vectorized
    for (int i = tid; i < 64 * 8; i += 256) {
        int d = i >> 3, qg = (i & 7) << 2;
        *(float4*)&sQ[d * 32 + qg] = *(const float4*)&g_Q[(h * HD + d) * HW + q0 + qg];
    }
    // preload K chunk 0
    {
        const float4* src = (const float4*)&g_K[(h * HD + dstg) * KP + cstg];
        float4 r0 = src[0], r1 = src[1], r2 = src[2], r3 = src[3];
        float4* dst = (float4*)&sKV0[dstg * 68 + cstg];
        dst[0] = r0; dst[1] = r1; dst[2] = r2; dst[3] = r3;
    }
    __syncthreads();

    // ---- Pass 1: E[q][k] = sum_d Q[d][q] * K[d][k] ----
    for (int kc = 0; kc < KP; kc += 64) {
        int cur = (kc >> 6) & 1;
        const float* cKV = sKVb[cur];
        bool pf = kc + 64 < KP;
        float4 r0, r1, r2, r3;
        if (pf) {
            const float4* src = (const float4*)&g_K[(h * HD + dstg) * KP + kc + 64 + cstg];
            r0 = src[0]; r1 = src[1]; r2 = src[2]; r3 = src[3];
        }
        ull e00 = 0, e01 = 0, e10 = 0, e11 = 0;
#pragma unroll 16
        for (int d = 0; d < 64; d++) {
            float2 a = *(const float2*)&sQ[d * 32 + (ty << 1)];
            float4 b = *(const float4*)&cKV[d * 68 + tx4];
            ull b01 = pk2(b.x, b.y), b23 = pk2(b.z, b.w);
            ull a0 = pk2(a.x, a.x), a1 = pk2(a.y, a.y);
            fma2(e00, a0, b01); fma2(e01, a0, b23);
            fma2(e10, a1, b01); fma2(e11, a1, b23);
        }
        {
            float2 p0 = upk(e00), p1 = upk(e01), p2 = upk(e10), p3 = upk(e11);
            int r = (ty << 1) * SE_STRIDE + kc + tx4;
            *(float4*)&sE[r]             = make_float4(p0.x, p0.y, p1.x, p1.y);
            *(float4*)&sE[r + SE_STRIDE] = make_float4(p2.x, p2.y, p3.x, p3.y);
        }
        if (pf) {
            float4* dst = (float4*)&sKVb[cur ^ 1][dstg * 68 + cstg];
            dst[0] = r0; dst[1] = r1; dst[2] = r2; dst[3] = r3;
        }
        __syncthreads();
    }

    // issue V chunk-0 global loads early; they complete under softmax
    float4 v0r, v1r, v2r, v3r;
    {
        const float4* src = (const float4*)&g_VT[dstg * C_ + h * HD + cstg];
        v0r = src[0]; v1r = src[1]; v2r = src[2]; v3r = src[3];
    }

    // ---- Multiplicity-weighted softmax, in place: P = mult*exp(E-max) ----
    {
        int row = tid >> 3, part = tid & 7;      // 8 threads per query row
        float* Er = &sE[row * SE_STRIDE];
        int i0 = part * 120;
        float m = -1e30f;
        for (int i = i0; i < i0 + 120; i++) m = fmaxf(m, Er[i]);
        m = fmaxf(m, __shfl_xor_sync(~0u, m, 1));
        m = fmaxf(m, __shfl_xor_sync(~0u, m, 2));
        m = fmaxf(m, __shfl_xor_sync(~0u, m, 4));
        float s = 0.f;
        for (int i = i0; i < i0 + 120; i++) {
            float w = 0.f;
            if (i < PP) {
                int pr = i / PW, pc = i - pr * PW;
                int mr = min(pr + 1, min(7, PW - pr));
                int mc = min(pc + 1, min(7, PW - pc));
                w = (float)(mr * mc);
            }
            float p = w * __expf(Er[i] - m);
            Er[i] = p;
            s += p;
        }
        s += __shfl_xor_sync(~0u, s, 1);
        s += __shfl_xor_sync(~0u, s, 2);
        s += __shfl_xor_sync(~0u, s, 4);
        if (part == 0) sInv[row] = 1.f / s;
    }
    // store V chunk 0 (pass 1 / softmax no longer touch sKV0)
    {
        float4* dst = (float4*)&sKV0[dstg * 68 + cstg];
        dst[0] = v0r; dst[1] = v1r; dst[2] = v2r; dst[3] = v3r;
    }
    __syncthreads();

    // ---- Pass 2: out[q][d] = sum_k P[q][k] * VT[k][d] ----
    ull o00 = 0, o01 = 0, o10 = 0, o11 = 0;
    for (int kc = 0; kc < KP; kc += 64) {
        int cur = (kc >> 6) & 1;
        const float* cKV = sKVb[cur];
        bool pf = kc + 64 < KP;
        float4 r0, r1, r2, r3;
        if (pf) {
            const float4* src = (const float4*)&g_VT[(kc + 64 + dstg) * C_ + h * HD + cstg];
            r0 = src[0]; r1 = src[1]; r2 = src[2]; r3 = src[3];
        }
        const float* sEr0 = &sE[(ty << 1) * SE_STRIDE + kc];
        const float* sEr1 = sEr0 + SE_STRIDE;
#pragma unroll 8
        for (int k = 0; k < 64; k += 2) {
            float2 pa = *(const float2*)&sEr0[k];
            float2 pb = *(const float2*)&sEr1[k];
            float4 va = *(const float4*)&cKV[k * 68 + tx4];
            float4 vb = *(const float4*)&cKV[(k + 1) * 68 + tx4];
            ull va01 = pk2(va.x, va.y), va23 = pk2(va.z, va.w);
            ull vb01 = pk2(vb.x, vb.y), vb23 = pk2(vb.z, vb.w);
            ull pax = pk2(pa.x, pa.x), pbx = pk2(pb.x, pb.x);
            ull pay = pk2(pa.y, pa.y), pby = pk2(pb.y, pb.y);
            fma2(o00, pax, va01); fma2(o01, pax, va23);
            fma2(o10, pbx, va01); fma2(o11, pbx, va23);
            fma2(o00, pay, vb01); fma2(o01, pay, vb23);
            fma2(o10, pby, vb01); fma2(o11, pby, vb23);
        }
        if (pf) {
            float4* dst = (float4*)&sKVb[cur ^ 1][dstg * 68 + cstg];
            dst[0] = r0; dst[1] = r1; dst[2] = r2; dst[3] = r3;
        }
        __syncthreads();
    }

    // ---- Epilogue via smem transpose: out = gamma*acc/denom + x, coalesced ----
    {
        float2 a0 = upk(o00), a1 = upk(o01), a2 = upk(o10), a3 = upk(o11);
        float v0[4] = {a0.x, a0.y, a1.x, a1.y};
        float v1[4] = {a2.x, a2.y, a3.x, a3.y};
        float* sOut = sKV0;                       // 64 x 33 <= 4352, loop-end sync passed
        int qr = ty << 1;
#pragma unroll
        for (int j = 0; j < 4; j++) {
            sOut[(tx4 + j) * 33 + qr]     = v0[j];
            sOut[(tx4 + j) * 33 + qr + 1] = v1[j];
        }
        __syncthreads();
        float g = *gamma_p;
        for (int i = tid; i < 64 * 32; i += 256) {
            int d = i >> 5, q = i & 31;
            int gi = (h * HD + d) * HW + q0 + q;
            out[gi] = g * sOut[d * 33 + q] * sInv[q] + x[gi];
        }
    }
}

// ---------------------------------------------------------------------------
extern "C" void kernel_launch(void* const* d_in, const int* in_sizes, int n_in,
                              void* d_out, int out_size) {
    const float* x     = (const float*)d_in[0];
    const float* Wq    = (const float*)d_in[1];
    const float* bq    = (const float*)d_in[2];
    const float* Wk    = (const float*)d_in[3];
    const float* bk    = (const float*)d_in[4];
    const float* Wv    = (const float*)d_in[5];
    const float* bv    = (const float*)d_in[6];
    const float* gamma = (const float*)d_in[7];
    float* out = (float*)d_out;

    pad_kernel<<<(C_ * KP + 255) / 256, 256>>>(x);
    gemm_all_kernel<<<312, 128>>>(Wq, bq, Wk, bk, Wv, bv, x);

    const int smem_bytes = (2048 + 2 * 4352 + 32 * SE_STRIDE + 32) * 4;  // 167040
    cudaFuncSetAttribute(attn_kernel, cudaFuncAttributeMaxDynamicSharedMemorySize, smem_bytes);
    attn_kernel<<<dim3(HW / 32, NH), 256, smem_bytes>>>(x, gamma, out);
}

// round 8
// speedup vs baseline: 1.4785x; 1.4785x over previous
#include <cuda_runtime.h>
#include <cstdint>

#define C_  512
#define Hh  24
#define Ww  24
#define HW  576
#define NH  8
#define HD  64
#define PW  30
#define PP  900
#define KP  960
#define SEW 964            /* sE row stride: 4 mod 32 -> conflict-free frag reads */

typedef unsigned long long ull;

// Scratch (device globals: allocation-free)
__device__ float g_Xp[C_ * KP];   // reflect-padded x, keys padded to 960 (zeros)
__device__ float g_QT[HW * C_];   // Q transposed: [p][o]
__device__ float g_KT[KP * C_];   // K transposed: [pp][o]
__device__ float g_V [C_ * KP];   // V: [o][pp]

// ---- tf32 tensor-core helpers ----
__device__ __forceinline__ uint32_t f2tf(float f) {
    uint32_t r; asm("cvt.rna.tf32.f32 %0, %1;" : "=r"(r) : "f"(f)); return r;
}
__device__ __forceinline__ void mma_tf32(float* c, const uint32_t* a, const uint32_t* b) {
    asm("mma.sync.aligned.m16n8k8.row.col.f32.tf32.tf32.f32 "
        "{%0,%1,%2,%3}, {%4,%5,%6,%7}, {%8,%9}, {%0,%1,%2,%3};"
        : "+f"(c[0]), "+f"(c[1]), "+f"(c[2]), "+f"(c[3])
        : "r"(a[0]), "r"(a[1]), "r"(a[2]), "r"(a[3]), "r"(b[0]), "r"(b[1]));
}

// ---------------------------------------------------------------------------
// Kernel 1: reflect-pad gather. g_Xp[c][pp] (pp = pr*30+pc), zeros for pp>=900.
// ---------------------------------------------------------------------------
__global__ void pad_kernel(const float* __restrict__ x) {
    int idx = blockIdx.x * 256 + threadIdx.x;
    if (idx >= C_ * KP) return;
    int c = idx / KP, pp = idx - c * KP;
    float v = 0.f;
    if (pp < PP) {
        int pr = pp / PW, pc = pp - pr * PW;
        int r = pr - 3; r = (r < 0) ? -r : ((r >= Hh) ? 2 * Hh - 2 - r : r);
        int cl = pc - 3; cl = (cl < 0) ? -cl : ((cl >= Ww) ? 2 * Ww - 2 - cl : cl);
        v = x[c * HW + r * Ww + cl];
    }
    g_Xp[idx] = v;
}

// ---------------------------------------------------------------------------
// Kernel 2: three conv1x1 GEMMs via mma.sync tf32 (R6-verbatim inner loop).
//   bid [0,72)   : QT = (Wq @ x )^T (N=576, transposed store)
//   bid [72,192) : KT = (Wk @ Xp)^T (N=960, transposed store)
//   bid [192,312): V  =  Wv @ Xp    (N=960, direct store)
// CTA tile 64o x 64n, 4 warps (2x2), warp tile 32x32. k-chunk 32, dbl-buffer.
// ---------------------------------------------------------------------------
__global__ void __launch_bounds__(128) gemm_all_kernel(
    const float* __restrict__ Wq, const float* __restrict__ bq,
    const float* __restrict__ Wk, const float* __restrict__ bk,
    const float* __restrict__ Wv, const float* __restrict__ bv,
    const float* __restrict__ x)
{
    __shared__ uint32_t smu[9216];   // sA0[2304] sA1[2304] sB0[2304] sB1[2304] = 36KB
    uint32_t* sA[2] = { smu,        smu + 2304 };   // [o][k] tf32, stride 36
    uint32_t* sB[2] = { smu + 4608, smu + 6912 };   // [k][n] tf32, stride 72

    int bid = blockIdx.x;
    const float *Wm, *bias, *X; float* Cout; int N, transp, nt, ot;
    if (bid < 72)       { nt = bid % 9;      ot = bid / 9;       Wm = Wq; bias = bq; X = x;    Cout = g_QT; N = HW; transp = 1; }
    else if (bid < 192) { int b = bid - 72;  nt = b % 15; ot = b / 15; Wm = Wk; bias = bk; X = g_Xp; Cout = g_KT; N = KP; transp = 1; }
    else                { int b = bid - 192; nt = b % 15; ot = b / 15; Wm = Wv; bias = bv; X = g_Xp; Cout = g_V;  N = KP; transp = 0; }
    int nB = nt * 64, oB = ot * 64;

    int tid  = threadIdx.x;
    int lane = tid & 31, wid = tid >> 5;
    int warp_m = wid & 1, warp_n = wid >> 1;     // 2x2 warps
    int grp = lane >> 2, qd = lane & 3;

    int arow = tid >> 1, ahalf = (tid & 1) << 4;     // A: 64 rows x 2 halves of 16
    int brow = tid >> 2, boff  = (tid & 3) << 4;     // B: 32 rows x 4 groups of 16

    float acc[2][4][4];
#pragma unroll
    for (int i = 0; i < 2; i++)
#pragma unroll
        for (int j = 0; j < 4; j++)
#pragma unroll
            for (int e = 0; e < 4; e++) acc[i][j][e] = 0.f;

    // stage chunk 0
    {
        const float4* aS = (const float4*)&Wm[(oB + arow) * C_ + ahalf];
        const float4* bS = (const float4*)&X[brow * N + nB + boff];
#pragma unroll
        for (int g = 0; g < 4; g++) {
            float4 w = aS[g];
            uint4 t = make_uint4(f2tf(w.x), f2tf(w.y), f2tf(w.z), f2tf(w.w));
            *(uint4*)&sA[0][arow * 36 + ahalf + 4 * g] = t;
        }
#pragma unroll
        for (int g = 0; g < 4; g++) {
            float4 v = bS[g];
            uint4 t = make_uint4(f2tf(v.x), f2tf(v.y), f2tf(v.z), f2tf(v.w));
            *(uint4*)&sB[0][brow * 72 + boff + 4 * g] = t;
        }
    }
    __syncthreads();

    int buf = 0;
    for (int cc = 0; cc < C_; cc += 32) {
        bool pf = cc + 32 < C_;
        float4 wreg[4], xreg[4];
        if (pf) {
            const float4* aS = (const float4*)&Wm[(oB + arow) * C_ + cc + 32 + ahalf];
            const float4* bS = (const float4*)&X[(cc + 32 + brow) * N + nB + boff];
#pragma unroll
            for (int g = 0; g < 4; g++) wreg[g] = aS[g];
#pragma unroll
            for (int g = 0; g < 4; g++) xreg[g] = bS[g];
        }
        const uint32_t* cA = sA[buf];
        const uint32_t* cB = sB[buf];
#pragma unroll
        for (int ks = 0; ks < 4; ks++) {
            int kb = ks << 3;
            uint32_t afr[2][4];
#pragma unroll
            for (int ms = 0; ms < 2; ms++) {
                int base = warp_m * 32 + ms * 16 + grp;
                afr[ms][0] = cA[(base    ) * 36 + kb + qd];
                afr[ms][1] = cA[(base + 8) * 36 + kb + qd];
                afr[ms][2] = cA[(base    ) * 36 + kb + 4 + qd];
                afr[ms][3] = cA[(base + 8) * 36 + kb + 4 + qd];
            }
            uint32_t bfr[4][2];
#pragma unroll
            for (int ns = 0; ns < 4; ns++) {
                int n = warp_n * 32 + ns * 8 + grp;
                bfr[ns][0] = cB[(kb + qd    ) * 72 + n];
                bfr[ns][1] = cB[(kb + 4 + qd) * 72 + n];
            }
#pragma unroll
            for (int ms = 0; ms < 2; ms++)
#pragma unroll
                for (int ns = 0; ns < 4; ns++)
                    mma_tf32(acc[ms][ns], afr[ms], bfr[ns]);
        }
        if (pf) {
            uint32_t* nA = sA[buf ^ 1];
            uint32_t* nBp = sB[buf ^ 1];
#pragma unroll
            for (int g = 0; g < 4; g++) {
                float4 w = wreg[g];
                uint4 t = make_uint4(f2tf(w.x), f2tf(w.y), f2tf(w.z), f2tf(w.w));
                *(uint4*)&nA[arow * 36 + ahalf + 4 * g] = t;
            }
#pragma unroll
            for (int g = 0; g < 4; g++) {
                float4 v = xreg[g];
                uint4 t = make_uint4(f2tf(v.x), f2tf(v.y), f2tf(v.z), f2tf(v.w));
                *(uint4*)&nBp[brow * 72 + boff + 4 * g] = t;
            }
        }
        __syncthreads();
        buf ^= 1;
    }

    // epilogue
    if (!transp) {
#pragma unroll
        for (int ms = 0; ms < 2; ms++)
#pragma unroll
            for (int part = 0; part < 2; part++) {
                int row = warp_m * 32 + ms * 16 + grp + part * 8;
                float bv_ = bias[oB + row];
#pragma unroll
                for (int ns = 0; ns < 4; ns++) {
                    float2 val = make_float2(acc[ms][ns][2 * part] + bv_,
                                             acc[ms][ns][2 * part + 1] + bv_);
                    *(float2*)&Cout[(oB + row) * N + nB + warp_n * 32 + ns * 8 + 2 * qd] = val;
                }
            }
    } else {
        float* sT = (float*)smu;                 // [n][o], 64 x 65 = 4160 <= 9216
#pragma unroll
        for (int ms = 0; ms < 2; ms++)
#pragma unroll
            for (int part = 0; part < 2; part++) {
                int row = warp_m * 32 + ms * 16 + grp + part * 8;
                float bv_ = bias[oB + row];
#pragma unroll
                for (int ns = 0; ns < 4; ns++) {
                    int n = warp_n * 32 + ns * 8 + 2 * qd;
                    sT[(n    ) * 65 + row] = acc[ms][ns][2 * part] + bv_;
                    sT[(n + 1) * 65 + row] = acc[ms][ns][2 * part + 1] + bv_;
                }
            }
        __syncthreads();
#pragma unroll
        for (int it = 0; it < 32; it++) {
            int idx = it * 128 + tid;
            int n = idx >> 6, o = idx & 63;
            Cout[(nB + n) * C_ + oB + o] = sT[n * 65 + o];
        }
    }
}

// ---------------------------------------------------------------------------
// Kernel 3: fused attention via mma.sync tf32. Grid (18,8) = 144 CTAs x 256.
// E = Q^T K (M=32q, N=960k, K=64d); weighted softmax; out = P V (N=64d, K=960).
// 8 warps: each owns an 8-wide n-slice of every 64-key chunk.
// Q fragments staged once; K/V chunks staged coalesced (R2 pattern) + tf32 cvt.
// ---------------------------------------------------------------------------
__global__ void __launch_bounds__(256) attn_kernel(const float* __restrict__ x,
                            const float* __restrict__ gamma_p,
                            float* __restrict__ out) {
    extern __shared__ float smd[];
    uint32_t* sQf = (uint32_t*)smd;        // 2048: A-frags [ms 2][ks 8][lane 32][4]
    float* sKV0 = smd + 2048;              // 64*68 = 4352 (tf32 bits)
    float* sKV1 = sKV0 + 4352;             // 4352
    float* sE   = sKV1 + 4352;             // 32*964 = 30848
    float* sInv = sE + 32 * SEW;           // 32

    int h   = blockIdx.y;
    int q0  = blockIdx.x * 32;
    int tid = threadIdx.x;
    int w = tid >> 5, lane = tid & 31, grp = lane >> 2, qd = lane & 3;
    int dstg = tid >> 2, cstg = (tid & 3) << 4;     // chunk staging: row, 16-col group
    float* sKVb[2] = { sKV0, sKV1 };

    // ---- Stage Q fragments (one-time): element (q,d) -> frag order ----
    {
        int q = tid >> 3, db = (tid & 7) << 3;
        float4 qa = *(const float4*)&g_QT[(q0 + q) * C_ + h * HD + db];
        float4 qb = *(const float4*)&g_QT[(q0 + q) * C_ + h * HD + db + 4];
        int ms = q >> 4, qg = q & 7, hi = (q >> 3) & 1;
        float qv[8] = {qa.x, qa.y, qa.z, qa.w, qb.x, qb.y, qb.z, qb.w};
#pragma unroll
        for (int e = 0; e < 8; e++) {
            int d = db + e;
            sQf[((ms * 8 + (d >> 3)) * 32 + (qg << 2) + (d & 3)) * 4 + hi + (((d >> 2) & 1) << 1)] = f2tf(qv[e]);
        }
    }
    // ---- preload K chunk 0: sK[key][68] tf32 ----
    {
        const float4* src = (const float4*)&g_KT[dstg * C_ + h * HD + cstg];
        uint32_t* dst = (uint32_t*)&sKV0[dstg * 68 + cstg];
#pragma unroll
        for (int j = 0; j < 4; j++) {
            float4 r = src[j];
            *(uint4*)&dst[4 * j] = make_uint4(f2tf(r.x), f2tf(r.y), f2tf(r.z), f2tf(r.w));
        }
    }
    __syncthreads();

    // ---- Pass 1: E[q][k], 15 chunks of 64 keys ----
    for (int kc = 0, c = 0; kc < KP; kc += 64, c++) {
        const uint32_t* cK = (const uint32_t*)sKVb[c & 1];
        bool pf = kc + 64 < KP;
        float4 r0, r1, r2, r3;
        if (pf) {
            const float4* src = (const float4*)&g_KT[(kc + 64 + dstg) * C_ + h * HD + cstg];
            r0 = src[0]; r1 = src[1]; r2 = src[2]; r3 = src[3];
        }
        float acc0[4] = {0.f, 0.f, 0.f, 0.f};
        float acc1[4] = {0.f, 0.f, 0.f, 0.f};
#pragma unroll
        for (int ks = 0; ks < 8; ks++) {
            uint4 a0 = *(const uint4*)&sQf[((    ks) * 32 + lane) * 4];
            uint4 a1 = *(const uint4*)&sQf[((8 + ks) * 32 + lane) * 4];
            uint32_t bf[2];
            bf[0] = cK[(w * 8 + grp) * 68 + ks * 8 + qd];
            bf[1] = cK[(w * 8 + grp) * 68 + ks * 8 + 4 + qd];
            mma_tf32(acc0, (const uint32_t*)&a0, bf);
            mma_tf32(acc1, (const uint32_t*)&a1, bf);
        }
        {
            int col = kc + w * 8 + 2 * qd;
            *(float2*)&sE[(grp     ) * SEW + col] = make_float2(acc0[0], acc0[1]);
            *(float2*)&sE[(grp +  8) * SEW + col] = make_float2(acc0[2], acc0[3]);
            *(float2*)&sE[(grp + 16) * SEW + col] = make_float2(acc1[0], acc1[1]);
            *(float2*)&sE[(grp + 24) * SEW + col] = make_float2(acc1[2], acc1[3]);
        }
        if (pf) {
            uint32_t* dst = (uint32_t*)&sKVb[(c & 1) ^ 1][dstg * 68 + cstg];
            *(uint4*)&dst[0]  = make_uint4(f2tf(r0.x), f2tf(r0.y), f2tf(r0.z), f2tf(r0.w));
            *(uint4*)&dst[4]  = make_uint4(f2tf(r1.x), f2tf(r1.y), f2tf(r1.z), f2tf(r1.w));
            *(uint4*)&dst[8]  = make_uint4(f2tf(r2.x), f2tf(r2.y), f2tf(r2.z), f2tf(r2.w));
            *(uint4*)&dst[12] = make_uint4(f2tf(r3.x), f2tf(r3.y), f2tf(r3.z), f2tf(r3.w));
        }
        __syncthreads();
    }

    // ---- prefetch V chunk 0 (completes under softmax): sV[d][key-chunk] ----
    float4 v0r, v1r, v2r, v3r;
    {
        const float4* src = (const float4*)&g_V[(h * HD + dstg) * KP + cstg];
        v0r = src[0]; v1r = src[1]; v2r = src[2]; v3r = src[3];
    }

    // ---- Multiplicity-weighted softmax; store tf32-rounded P in place ----
    {
        int row = tid >> 3, part = tid & 7;      // 8 threads per query row
        float* Er = &sE[row * SEW];
        int i0 = part * 120;
        float m = -1e30f;
        for (int i = i0; i < i0 + 120; i++) m = fmaxf(m, Er[i]);
        m = fmaxf(m, __shfl_xor_sync(~0u, m, 1));
        m = fmaxf(m, __shfl_xor_sync(~0u, m, 2));
        m = fmaxf(m, __shfl_xor_sync(~0u, m, 4));
        float s = 0.f;
        for (int i = i0; i < i0 + 120; i++) {
            float wgt = 0.f;
            if (i < PP) {
                int pr = i / PW, pc = i - pr * PW;
                int mr = min(pr + 1, min(7, PW - pr));
                int mc = min(pc + 1, min(7, PW - pc));
                wgt = (float)(mr * mc);
            }
            float p = __uint_as_float(f2tf(wgt * __expf(Er[i] - m)));
            Er[i] = p;
            s += p;
        }
        s += __shfl_xor_sync(~0u, s, 1);
        s += __shfl_xor_sync(~0u, s, 2);
        s += __shfl_xor_sync(~0u, s, 4);
        if (part == 0) sInv[row] = 1.f / s;
    }
    // store V chunk 0 into sKV0 (E-pass finished with it at final sync)
    {
        uint32_t* dst = (uint32_t*)&sKV0[dstg * 68 + cstg];
        *(uint4*)&dst[0]  = make_uint4(f2tf(v0r.x), f2tf(v0r.y), f2tf(v0r.z), f2tf(v0r.w));
        *(uint4*)&dst[4]  = make_uint4(f2tf(v1r.x), f2tf(v1r.y), f2tf(v1r.z), f2tf(v1r.w));
        *(uint4*)&dst[8]  = make_uint4(f2tf(v2r.x), f2tf(v2r.y), f2tf(v2r.z), f2tf(v2r.w));
        *(uint4*)&dst[12] = make_uint4(f2tf(v3r.x), f2tf(v3r.y), f2tf(v3r.z), f2tf(v3r.w));
    }
    __syncthreads();

    // ---- Pass 2: out = P V. M=32q, N=64d (warp w owns d slice w*8..w*8+7) ----
    float o0[4] = {0.f, 0.f, 0.f, 0.f};
    float o1[4] = {0.f, 0.f, 0.f, 0.f};
    for (int kc = 0, c = 0; kc < KP; kc += 64, c++) {
        const uint32_t* cV = (const uint32_t*)sKVb[c & 1];
        bool pf = kc + 64 < KP;
        float4 r0, r1, r2, r3;
        if (pf) {
            const float4* src = (const float4*)&g_V[(h * HD + dstg) * KP + kc + 64 + cstg];
            r0 = src[0]; r1 = src[1]; r2 = src[2]; r3 = src[3];
        }
#pragma unroll
        for (int ks = 0; ks < 8; ks++) {
            int colb = kc + ks * 8;
            uint32_t a0[4], a1[4], bf[2];
            a0[0] = __float_as_uint(sE[(grp     ) * SEW + colb + qd]);
            a0[1] = __float_as_uint(sE[(grp +  8) * SEW + colb + qd]);
            a0[2] = __float_as_uint(sE[(grp     ) * SEW + colb + 4 + qd]);
            a0[3] = __float_as_uint(sE[(grp +  8) * SEW + colb + 4 + qd]);
            a1[0] = __float_as_uint(sE[(grp + 16) * SEW + colb + qd]);
            a1[1] = __float_as_uint(sE[(grp + 24) * SEW + colb + qd]);
            a1[2] = __float_as_uint(sE[(grp + 16) * SEW + colb + 4 + qd]);
            a1[3] = __float_as_uint(sE[(grp + 24) * SEW + colb + 4 + qd]);
            bf[0] = cV[(w * 8 + grp) * 68 + ks * 8 + qd];
            bf[1] = cV[(w * 8 + grp) * 68 + ks * 8 + 4 + qd];
            mma_tf32(o0, a0, bf);
            mma_tf32(o1, a1, bf);
        }
        if (pf) {
            uint32_t* dst = (uint32_t*)&sKVb[(c & 1) ^ 1][dstg * 68 + cstg];
            *(uint4*)&dst[0]  = make_uint4(f2tf(r0.x), f2tf(r0.y), f2tf(r0.z), f2tf(r0.w));
            *(uint4*)&dst[4]  = make_uint4(f2tf(r1.x), f2tf(r1.y), f2tf(r1.z), f2tf(r1.w));
            *(uint4*)&dst[8]  = make_uint4(f2tf(r2.x), f2tf(r2.y), f2tf(r2.z), f2tf(r2.w));
            *(uint4*)&dst[12] = make_uint4(f2tf(r3.x), f2tf(r3.y), f2tf(r3.z), f2tf(r3.w));
        }
        __syncthreads();
    }

    // ---- Epilogue via smem transpose: out = gamma*acc/denom + x ----
    {
        float* sT = sKV0;                        // [d][q] 64 x 33 = 2112 <= 4352
        int dc = w * 8 + 2 * qd;
        sT[(dc    ) * 33 + grp     ] = o0[0];
        sT[(dc + 1) * 33 + grp     ] = o0[1];
        sT[(dc    ) * 33 + grp +  8] = o0[2];
        sT[(dc + 1) * 33 + grp +  8] = o0[3];
        sT[(dc    ) * 33 + grp + 16] = o1[0];
        sT[(dc + 1) * 33 + grp + 16] = o1[1];
        sT[(dc    ) * 33 + grp + 24] = o1[2];
        sT[(dc + 1) * 33 + grp + 24] = o1[3];
        __syncthreads();
        float g = *gamma_p;
        for (int i = tid; i < 64 * 32; i += 256) {
            int d = i >> 5, q = i & 31;
            int gi = (h * HD + d) * HW + q0 + q;
            out[gi] = g * sT[d * 33 + q] * sInv[q] + x[gi];
        }
    }
}

// ---------------------------------------------------------------------------
extern "C" void kernel_launch(void* const* d_in, const int* in_sizes, int n_in,
                              void* d_out, int out_size) {
    const float* x     = (const float*)d_in[0];
    const float* Wq    = (const float*)d_in[1];
    const float* bq    = (const float*)d_in[2];
    const float* Wk    = (const float*)d_in[3];
    const float* bk    = (const float*)d_in[4];
    const float* Wv    = (const float*)d_in[5];
    const float* bv    = (const float*)d_in[6];
    const float* gamma = (const float*)d_in[7];
    float* out = (float*)d_out;

    pad_kernel<<<(C_ * KP + 255) / 256, 256>>>(x);
    gemm_all_kernel<<<312, 128>>>(Wq, bq, Wk, bk, Wv, bv, x);

    const int smem_bytes = (2048 + 2 * 4352 + 32 * SEW + 32) * 4;  // 166528
    cudaFuncSetAttribute(attn_kernel, cudaFuncAttributeMaxDynamicSharedMemorySize, smem_bytes);
    attn_kernel<<<dim3(HW / 32, NH), 256, smem_bytes>>>(x, gamma, out);
}